// round 15
// baseline (speedup 1.0000x reference)
#include <cuda_runtime.h>
#include <cuda_bf16.h>
#include <math.h>

#define B_  8
#define S_  2048
#define H_  1024
#define D_  64
#define M_TOT (B_*S_)   // 16384

// Scratch (device globals = legal scratch). q/k row-major [b][s][d] bf16 hi/lo;
// v tile-transposed [b][s/64][d][s%64] bf16 hi/lo.
__device__ __align__(16) __nv_bfloat16 g_qh[M_TOT * D_];
__device__ __align__(16) __nv_bfloat16 g_ql[M_TOT * D_];
__device__ __align__(16) __nv_bfloat16 g_kh[M_TOT * D_];
__device__ __align__(16) __nv_bfloat16 g_kl[M_TOT * D_];
__device__ __align__(16) __nv_bfloat16 g_vth[M_TOT * D_];
__device__ __align__(16) __nv_bfloat16 g_vtl[M_TOT * D_];
__device__ __align__(16) __nv_bfloat16 g_wt[6 * 64 * 1024];   // [mat*2+split][n][k]

typedef unsigned long long u64;
typedef unsigned int u32;

__device__ __forceinline__ u32 smem_u32(const void* p) {
    u32 a;
    asm("{ .reg .u64 t; cvta.to.shared.u64 t, %1; cvt.u32.u64 %0, t; }"
        : "=r"(a) : "l"(p));
    return a;
}

// ---- mma.sync (sm_80-era HMMA path; compiles under plain compute_103) ----
#define MMA_BF16(d, a, b) \
    asm volatile("mma.sync.aligned.m16n8k16.row.col.f32.bf16.bf16.f32 " \
        "{%0,%1,%2,%3}, {%4,%5,%6,%7}, {%8,%9}, {%0,%1,%2,%3};" \
        : "+f"((d)[0]), "+f"((d)[1]), "+f"((d)[2]), "+f"((d)[3]) \
        : "r"((a)[0]), "r"((a)[1]), "r"((a)[2]), "r"((a)[3]), \
          "r"((b)[0]), "r"((b)[1]))

#define LDSM_X4(r, addr) \
    asm volatile("ldmatrix.sync.aligned.m8n8.x4.shared.b16 {%0,%1,%2,%3}, [%4];" \
        : "=r"((r)[0]), "=r"((r)[1]), "=r"((r)[2]), "=r"((r)[3]) : "r"(addr))

#define LDSM_X2(r, addr) \
    asm volatile("ldmatrix.sync.aligned.m8n8.x2.shared.b16 {%0,%1}, [%2];" \
        : "=r"((r)[0]), "=r"((r)[1]) : "r"(addr))

// split a pair of fp32 into packed bf16 hi and lo words
__device__ __forceinline__ void bsplit2(float a, float b, u32 &hi, u32 &lo) {
    __nv_bfloat16 ha = __float2bfloat16(a), hb = __float2bfloat16(b);
    float ra = a - __bfloat162float(ha), rb = b - __bfloat162float(hb);
    __nv_bfloat16 la = __float2bfloat16(ra), lb = __float2bfloat16(rb);
    hi = (u32)__bfloat16_as_ushort(ha) | ((u32)__bfloat16_as_ushort(hb) << 16);
    lo = (u32)__bfloat16_as_ushort(la) | ((u32)__bfloat16_as_ushort(lb) << 16);
}

// byte offset inside a 64-row x 128B tile, XOR-swizzled for conflict-free ldmatrix
__device__ __forceinline__ u32 off128(int row, int quad) {
    return (u32)((row << 7) + (((quad ^ (row & 7)) << 4)));
}

// ============================================================================
// One-time W transpose + bf16 hi/lo split: g_wt[mat*2+split][n][k]
// ============================================================================
__global__ void wsplit_kernel(const float* __restrict__ Wq,
                              const float* __restrict__ Wk,
                              const float* __restrict__ Wv)
{
    int idx = blockIdx.x * 256 + threadIdx.x;
    int k   = idx & 1023;
    int n   = (idx >> 10) & 63;
    int mat = idx >> 16;
    const float* W = (mat == 0) ? Wq : (mat == 1) ? Wk : Wv;
    float x = W[k * 64 + n];
    __nv_bfloat16 h = __float2bfloat16(x);
    float r = x - __bfloat162float(h);
    __nv_bfloat16 l = __float2bfloat16(r);
    g_wt[(mat * 2 + 0) * 65536 + n * 1024 + k] = h;
    g_wt[(mat * 2 + 1) * 65536 + n * 1024 + k] = l;
}

// ============================================================================
// QKV projection via mma.sync bf16 3-pass split (validated). Writes q/k/v as
// bf16 hi/lo (q/k row-major, v tile-transposed).
// ============================================================================
__global__ void __launch_bounds__(256) qkv_mma_kernel(
    const float* __restrict__ x,
    const float* __restrict__ bq, const float* __restrict__ bk,
    const float* __restrict__ bv)
{
    __shared__ __align__(16) char sA[2][2][128 * 32];
    __shared__ __align__(16) char sB[2][2][192 * 32];
    __shared__ float bias_s[192];

    const int tid    = threadIdx.x;
    const int lane   = tid & 31;
    const int wid    = tid >> 5;
    const int warp_m = wid >> 1;
    const int warp_n = wid & 1;
    const int mBase  = blockIdx.x * 128;

    if (tid < 192)
        bias_s[tid] = (tid < 64) ? bq[tid]
                    : (tid < 128) ? bk[tid - 64] : bv[tid - 128];

    const u32 aBase = smem_u32(sA);
    const u32 bBase = smem_u32(sB);

    float acc[2][12][4];
    #pragma unroll
    for (int mt = 0; mt < 2; mt++)
        #pragma unroll
        for (int nt = 0; nt < 12; nt++)
            #pragma unroll
            for (int e = 0; e < 4; e++) acc[mt][nt][e] = 0.f;

    const int xr = tid >> 1, xq = tid & 1;
    const u32 xoff = xr * 32 + ((xq ^ ((xr >> 2) & 1)) << 4);
    const float* xsrc = &x[(size_t)(mBase + xr) * H_ + xq * 8];

    int w_split[3], w_srcoff[3]; u32 w_off[3];
    #pragma unroll
    for (int i = 0; i < 3; i++) {
        int q = i * 256 + tid;
        int ms = q >> 7;
        int idx = q & 127;
        int nn = idx >> 1, qq = idx & 1;
        int r  = (ms >> 1) * 64 + nn;
        w_split[i] = ms & 1;
        w_srcoff[i] = (ms * 64 + nn) * 1024 + qq * 8;
        w_off[i] = r * 32 + ((qq ^ ((r >> 2) & 1)) << 4);
    }

    u32 a_off[2];
    {
        int arow = warp_m * 32 + (lane & 15);
        u32 aq = lane >> 4;
        #pragma unroll
        for (int mt = 0; mt < 2; mt++) {
            int r = arow + mt * 16;
            a_off[mt] = r * 32 + ((aq ^ ((r >> 2) & 1)) << 4);
        }
    }
    u32 b_off[12];
    {
        int brow = lane & 7;
        u32 bqd = (lane >> 3) & 1;
        #pragma unroll
        for (int nt = 0; nt < 12; nt++) {
            int r = warp_n * 96 + nt * 8 + brow;
            b_off[nt] = r * 32 + ((bqd ^ ((r >> 2) & 1)) << 4);
        }
    }

    float4 xv0 = *(const float4*)(xsrc);
    float4 xv1 = *(const float4*)(xsrc + 4);
    uint4 wv[3];
    #pragma unroll
    for (int i = 0; i < 3; i++)
        wv[i] = *(const uint4*)&g_wt[w_srcoff[i]];

    for (int c = 0; c < 64; ++c) {
        const int buf = c & 1;
        {
            float f[8] = { xv0.x, xv0.y, xv0.z, xv0.w, xv1.x, xv1.y, xv1.z, xv1.w };
            u32 hp[4], lp[4];
            #pragma unroll
            for (int j = 0; j < 4; ++j)
                bsplit2(f[2*j], f[2*j+1], hp[j], lp[j]);
            *(uint4*)&sA[buf][0][xoff] = make_uint4(hp[0], hp[1], hp[2], hp[3]);
            *(uint4*)&sA[buf][1][xoff] = make_uint4(lp[0], lp[1], lp[2], lp[3]);
            #pragma unroll
            for (int i = 0; i < 3; i++)
                *(uint4*)&sB[buf][w_split[i]][w_off[i]] = wv[i];
        }
        __syncthreads();

        if (c < 63) {
            xv0 = *(const float4*)(xsrc + (c + 1) * 16);
            xv1 = *(const float4*)(xsrc + (c + 1) * 16 + 4);
            #pragma unroll
            for (int i = 0; i < 3; i++)
                wv[i] = *(const uint4*)&g_wt[w_srcoff[i] + (c + 1) * 16];
        }

        const u32 aH = aBase + (buf * 2 + 0) * 4096;
        const u32 aL = aBase + (buf * 2 + 1) * 4096;
        const u32 bH = bBase + (buf * 2 + 0) * 6144;
        const u32 bL = bBase + (buf * 2 + 1) * 6144;

        u32 ah[2][4], al[2][4];
        #pragma unroll
        for (int mt = 0; mt < 2; mt++) {
            LDSM_X4(ah[mt], aH + a_off[mt]);
            LDSM_X4(al[mt], aL + a_off[mt]);
        }
        #pragma unroll
        for (int nt = 0; nt < 12; nt++) {
            u32 bh[2], bl[2];
            LDSM_X2(bh, bH + b_off[nt]);
            LDSM_X2(bl, bL + b_off[nt]);
            #pragma unroll
            for (int mt = 0; mt < 2; mt++) {
                MMA_BF16(acc[mt][nt], ah[mt], bh);
                MMA_BF16(acc[mt][nt], ah[mt], bl);
                MMA_BF16(acc[mt][nt], al[mt], bh);
            }
        }
        __syncthreads();
    }

    // ---- epilogue: bias add, bf16 hi/lo split outputs ----
    #pragma unroll
    for (int mt = 0; mt < 2; mt++) {
        #pragma unroll
        for (int nt = 0; nt < 12; nt++) {
            const int ng  = warp_n * 96 + nt * 8 + (lane & 3) * 2;
            const int mat = ng >> 6;
            const int col = ng & 63;
            const int r0  = mBase + warp_m * 32 + mt * 16 + (lane >> 2);
            const float b0 = bias_s[ng], b1 = bias_s[ng + 1];
            const float v00 = acc[mt][nt][0] + b0, v01 = acc[mt][nt][1] + b1;
            const float v10 = acc[mt][nt][2] + b0, v11 = acc[mt][nt][3] + b1;
            if (mat < 2) {
                __nv_bfloat16* dh = mat ? g_kh : g_qh;
                __nv_bfloat16* dl = mat ? g_kl : g_ql;
                u32 h0, l0, h1, l1;
                bsplit2(v00, v01, h0, l0);
                bsplit2(v10, v11, h1, l1);
                *(u32*)&dh[(size_t)r0 * D_ + col]       = h0;
                *(u32*)&dl[(size_t)r0 * D_ + col]       = l0;
                *(u32*)&dh[(size_t)(r0 + 8) * D_ + col] = h1;
                *(u32*)&dl[(size_t)(r0 + 8) * D_ + col] = l1;
            } else {
                #pragma unroll
                for (int e = 0; e < 4; e++) {
                    const int rr = r0 + (e >> 1) * 8;
                    const int cc = col + (e & 1);
                    const float vv = (e == 0) ? v00 : (e == 1) ? v01 : (e == 2) ? v10 : v11;
                    const int bb = rr >> 11, ss = rr & 2047;
                    const int tile = ss >> 6, kk = ss & 63;
                    size_t idx = (((size_t)bb * 32 + tile) * 64 + cc) * 64 + kk;
                    __nv_bfloat16 h = __float2bfloat16(vv);
                    float r = vv - __bfloat162float(h);
                    g_vth[idx] = h;
                    g_vtl[idx] = __float2bfloat16(r);
                }
            }
        }
    }
}

// ============================================================================
// Causal flash attention, mma.sync bf16, register-resident P:
//  - Q fragments hoisted out of the key loop (tile-invariant)
//  - softmax packs P directly into pass-2 A fragments (C-frag == A-frag rows)
//    -> no P smem staging, no pass-2 A ldmatrix, only 2 syncthreads/tile
//  - B operands ldmatrix.x4 over n-tile pairs (half the LDSM count)
// Grid 32 x 8, heavy-first (mIdx = 31 - blockIdx.x); 128 threads = 4 warps,
// warp w owns rows [w*16, w*16+16). out = (softmax(QK^T masked)/32) @ V.
// ============================================================================
__global__ void __launch_bounds__(128) attn_kernel(float* __restrict__ out)
{
    const int b    = blockIdx.y;
    const int mIdx = 31 - blockIdx.x;        // heavy CTAs launch first
    const int mBase = mIdx * 64;
    const int tid  = threadIdx.x;
    const int lane = tid & 31;
    const int wid  = tid >> 5;

    __shared__ __align__(16) char sQ[2][8192];   // Q hi/lo, 64 rows x 128B
    __shared__ __align__(16) char sK[2][8192];   // K hi/lo
    __shared__ __align__(16) char sV[2][8192];   // Vt hi/lo

    const u32 aQ0 = smem_u32(sQ[0]), aQ1 = smem_u32(sQ[1]);
    const u32 aK0 = smem_u32(sK[0]), aK1 = smem_u32(sK[1]);
    const u32 aV0 = smem_u32(sV[0]), aV1 = smem_u32(sV[1]);

    const __nv_bfloat16* gqh = g_qh  + (size_t)b * S_ * D_;
    const __nv_bfloat16* gql = g_ql  + (size_t)b * S_ * D_;
    const __nv_bfloat16* gkh = g_kh  + (size_t)b * S_ * D_;
    const __nv_bfloat16* gkl = g_kl  + (size_t)b * S_ * D_;
    const __nv_bfloat16* gvh = g_vth + (size_t)b * S_ * D_;
    const __nv_bfloat16* gvl = g_vtl + (size_t)b * S_ * D_;
    float* gout = out + (size_t)b * S_ * D_;

    // fragment geometry
    const int aRow  = wid * 16 + (lane & 15);
    const int aQd   = lane >> 4;                 // k16-half for A ldmatrix.x4
    const int bRow4 = ((lane >> 4) << 3) + (lane & 7);  // + ntPair*16
    const int bQd   = (lane >> 3) & 1;           // k8-half within k16
    const int rl    = wid * 16 + (lane >> 2);    // acc-frag row (c0/c1)
    const int rh    = rl + 8;                    // acc-frag row (c2/c3)
    const int cB    = (lane & 3) * 2;            // col within n-tile

    // stage Q tile (bf16 hi/lo, swizzled)
    #pragma unroll
    for (int i = 0; i < 8; i++) {
        int idx = i * 128 + tid;
        int sp  = idx >> 9, r = (idx >> 3) & 63, qd = idx & 7;
        const __nv_bfloat16* src = (sp ? gql : gqh) + (size_t)(mBase + r) * D_ + qd * 8;
        *(uint4*)&sQ[sp][off128(r, qd)] = *(const uint4*)src;
    }
    __syncthreads();

    // hoist Q fragments (tile-invariant): 32 regs
    u32 qfh[4][4], qfl[4][4];
    #pragma unroll
    for (int kc = 0; kc < 4; kc++) {
        const u32 aoff = off128(aRow, 2 * kc + aQd);
        LDSM_X4(qfh[kc], aQ0 + aoff);
        LDSM_X4(qfl[kc], aQ1 + aoff);
    }

    float accO[8][4];
    #pragma unroll
    for (int nt = 0; nt < 8; nt++)
        #pragma unroll
        for (int e = 0; e < 4; e++) accO[nt][e] = 0.f;
    float m0 = -1e30f, m1 = -1e30f, l0 = 0.f, l1 = 0.f;

    for (int t = 0; t <= mIdx; t++) {
        __syncthreads();   // prev tile's K/V reads complete before overwrite
        #pragma unroll
        for (int i = 0; i < 16; i++) {
            int idx = i * 128 + tid;
            int tensor = idx >> 10, sp = (idx >> 9) & 1;
            int r = (idx >> 3) & 63, qd = idx & 7;
            const __nv_bfloat16* src;
            if (tensor == 0)
                src = (sp ? gkl : gkh) + (size_t)(t * 64 + r) * D_ + qd * 8;
            else
                src = (sp ? gvl : gvh) + (size_t)(t * 64 + r) * D_ + qd * 8;
            char* dst = tensor ? sV[sp] : sK[sp];
            *(uint4*)&dst[off128(r, qd)] = *(const uint4*)src;
        }
        __syncthreads();

        // ---- pass 1: S = Q K^T (3-pass bf16 split), B via x4 over nt pairs ----
        float accS[8][4];
        #pragma unroll
        for (int nt = 0; nt < 8; nt++)
            #pragma unroll
            for (int e = 0; e < 4; e++) accS[nt][e] = 0.f;

        #pragma unroll
        for (int kc = 0; kc < 4; kc++) {
            #pragma unroll
            for (int np = 0; np < 4; np++) {
                const u32 boff = off128(np * 16 + bRow4, 2 * kc + bQd);
                u32 bh[4], bl[4];
                LDSM_X4(bh, aK0 + boff);
                LDSM_X4(bl, aK1 + boff);
                MMA_BF16(accS[2*np],   qfh[kc], bh);
                MMA_BF16(accS[2*np],   qfh[kc], bl);
                MMA_BF16(accS[2*np],   qfl[kc], bh);
                MMA_BF16(accS[2*np+1], qfh[kc], bh + 2);
                MMA_BF16(accS[2*np+1], qfh[kc], bl + 2);
                MMA_BF16(accS[2*np+1], qfl[kc], bh + 2);
            }
        }

        // ---- online softmax on fragments; P packed straight into A-frags ----
        if (t == mIdx) {
            #pragma unroll
            for (int nt = 0; nt < 8; nt++) {
                const int c0 = nt * 8 + cB;
                if (c0 > rl)     accS[nt][0] = -1e30f;
                if (c0 + 1 > rl) accS[nt][1] = -1e30f;
                if (c0 > rh)     accS[nt][2] = -1e30f;
                if (c0 + 1 > rh) accS[nt][3] = -1e30f;
            }
        }
        float mx0 = -1e30f, mx1 = -1e30f;
        #pragma unroll
        for (int nt = 0; nt < 8; nt++) {
            mx0 = fmaxf(mx0, fmaxf(accS[nt][0], accS[nt][1]));
            mx1 = fmaxf(mx1, fmaxf(accS[nt][2], accS[nt][3]));
        }
        mx0 = fmaxf(mx0, __shfl_xor_sync(0xffffffffu, mx0, 1));
        mx0 = fmaxf(mx0, __shfl_xor_sync(0xffffffffu, mx0, 2));
        mx1 = fmaxf(mx1, __shfl_xor_sync(0xffffffffu, mx1, 1));
        mx1 = fmaxf(mx1, __shfl_xor_sync(0xffffffffu, mx1, 2));

        const float mn0 = fmaxf(m0, mx0), mn1 = fmaxf(m1, mx1);
        const float cr0 = __expf(m0 - mn0), cr1 = __expf(m1 - mn1);
        m0 = mn0; m1 = mn1;

        // P fragments: ph[nt][0] = rows g (pack p00,p01); [1] = rows g+8
        u32 ph[8][2], pl[8][2];
        float ps0 = 0.f, ps1 = 0.f;
        #pragma unroll
        for (int nt = 0; nt < 8; nt++) {
            const float p00 = __expf(accS[nt][0] - mn0);
            const float p01 = __expf(accS[nt][1] - mn0);
            const float p10 = __expf(accS[nt][2] - mn1);
            const float p11 = __expf(accS[nt][3] - mn1);
            ps0 += p00 + p01;
            ps1 += p10 + p11;
            bsplit2(p00, p01, ph[nt][0], pl[nt][0]);
            bsplit2(p10, p11, ph[nt][1], pl[nt][1]);
        }
        ps0 += __shfl_xor_sync(0xffffffffu, ps0, 1);
        ps0 += __shfl_xor_sync(0xffffffffu, ps0, 2);
        ps1 += __shfl_xor_sync(0xffffffffu, ps1, 1);
        ps1 += __shfl_xor_sync(0xffffffffu, ps1, 2);
        l0 = l0 * cr0 + ps0;
        l1 = l1 * cr1 + ps1;
        #pragma unroll
        for (int nt = 0; nt < 8; nt++) {
            accO[nt][0] *= cr0; accO[nt][1] *= cr0;
            accO[nt][2] *= cr1; accO[nt][3] *= cr1;
        }

        // ---- pass 2: O += P V ; A = register P, B = Vt[d][key] via x4 ----
        #pragma unroll
        for (int kc = 0; kc < 4; kc++) {
            // A-frag = {(g,klo),(g+8,klo),(g,khi),(g+8,khi)} = C-frags of
            // n-tiles 2kc (keys klo) and 2kc+1 (keys khi)
            u32 ah[4] = { ph[2*kc][0], ph[2*kc][1], ph[2*kc+1][0], ph[2*kc+1][1] };
            u32 al[4] = { pl[2*kc][0], pl[2*kc][1], pl[2*kc+1][0], pl[2*kc+1][1] };
            #pragma unroll
            for (int np = 0; np < 4; np++) {
                const u32 boff = off128(np * 16 + bRow4, 2 * kc + bQd);
                u32 bh[4], bl[4];
                LDSM_X4(bh, aV0 + boff);
                LDSM_X4(bl, aV1 + boff);
                MMA_BF16(accO[2*np],   ah, bh);
                MMA_BF16(accO[2*np],   ah, bl);
                MMA_BF16(accO[2*np],   al, bh);
                MMA_BF16(accO[2*np+1], ah, bh + 2);
                MMA_BF16(accO[2*np+1], ah, bl + 2);
                MMA_BF16(accO[2*np+1], al, bh + 2);
            }
        }
    }

    // ---- epilogue: /l (softmax norm) and /sqrt(H)=32 ----
    const float i0 = 1.0f / (l0 * 32.0f);
    const float i1 = 1.0f / (l1 * 32.0f);
    #pragma unroll
    for (int nt = 0; nt < 8; nt++) {
        const int col = nt * 8 + cB;
        *(float2*)&gout[(size_t)(mBase + rl) * D_ + col] =
            make_float2(accO[nt][0] * i0, accO[nt][1] * i0);
        *(float2*)&gout[(size_t)(mBase + rh) * D_ + col] =
            make_float2(accO[nt][2] * i1, accO[nt][3] * i1);
    }
}

extern "C" void kernel_launch(void* const* d_in, const int* in_sizes, int n_in,
                              void* d_out, int out_size)
{
    const float* x  = (const float*)d_in[0];
    const float* Wq = (const float*)d_in[1];
    const float* bq = (const float*)d_in[2];
    const float* Wk = (const float*)d_in[3];
    const float* bk = (const float*)d_in[4];
    const float* Wv = (const float*)d_in[5];
    const float* bv = (const float*)d_in[6];
    float* out = (float*)d_out;

    wsplit_kernel<<<768, 256>>>(Wq, Wk, Wv);
    qkv_mma_kernel<<<128, 256>>>(x, bq, bk, bv);
    attn_kernel<<<dim3(32, B_), 128>>>(out);
}

// round 16
// speedup vs baseline: 1.1680x; 1.1680x over previous
#include <cuda_runtime.h>
#include <cuda_bf16.h>
#include <math.h>

#define B_  8
#define S_  2048
#define H_  1024
#define D_  64
#define M_TOT (B_*S_)   // 16384

// Scratch (device globals = legal scratch). q/k row-major [b][s][d] bf16 hi/lo;
// v tile-transposed [b][s/64][d][s%64] bf16 hi/lo.
__device__ __align__(16) __nv_bfloat16 g_qh[M_TOT * D_];
__device__ __align__(16) __nv_bfloat16 g_ql[M_TOT * D_];
__device__ __align__(16) __nv_bfloat16 g_kh[M_TOT * D_];
__device__ __align__(16) __nv_bfloat16 g_kl[M_TOT * D_];
__device__ __align__(16) __nv_bfloat16 g_vth[M_TOT * D_];
__device__ __align__(16) __nv_bfloat16 g_vtl[M_TOT * D_];
__device__ __align__(16) __nv_bfloat16 g_wt[6 * 64 * 1024];   // [mat*2+split][n][k]

typedef unsigned long long u64;
typedef unsigned int u32;

__device__ __forceinline__ u32 smem_u32(const void* p) {
    u32 a;
    asm("{ .reg .u64 t; cvta.to.shared.u64 t, %1; cvt.u32.u64 %0, t; }"
        : "=r"(a) : "l"(p));
    return a;
}

// ---- mma.sync (sm_80-era HMMA path; compiles under plain compute_103) ----
#define MMA_BF16(d, a, b) \
    asm volatile("mma.sync.aligned.m16n8k16.row.col.f32.bf16.bf16.f32 " \
        "{%0,%1,%2,%3}, {%4,%5,%6,%7}, {%8,%9}, {%0,%1,%2,%3};" \
        : "+f"((d)[0]), "+f"((d)[1]), "+f"((d)[2]), "+f"((d)[3]) \
        : "r"((a)[0]), "r"((a)[1]), "r"((a)[2]), "r"((a)[3]), \
          "r"((b)[0]), "r"((b)[1]))

#define LDSM_X4(r, addr) \
    asm volatile("ldmatrix.sync.aligned.m8n8.x4.shared.b16 {%0,%1,%2,%3}, [%4];" \
        : "=r"((r)[0]), "=r"((r)[1]), "=r"((r)[2]), "=r"((r)[3]) : "r"(addr))

#define LDSM_X2(r, addr) \
    asm volatile("ldmatrix.sync.aligned.m8n8.x2.shared.b16 {%0,%1}, [%2];" \
        : "=r"((r)[0]), "=r"((r)[1]) : "r"(addr))

// ---- cp.async (Ampere-era LDGSTS path) ----
#define CP_ASYNC16(dst, src) \
    asm volatile("cp.async.cg.shared.global [%0], [%1], 16;" \
                 :: "r"(dst), "l"(src) : "memory")
#define CP_COMMIT() asm volatile("cp.async.commit_group;" ::: "memory")
#define CP_WAIT1()  asm volatile("cp.async.wait_group 1;" ::: "memory")

// split a pair of fp32 into packed bf16 hi and lo words
__device__ __forceinline__ void bsplit2(float a, float b, u32 &hi, u32 &lo) {
    __nv_bfloat16 ha = __float2bfloat16(a), hb = __float2bfloat16(b);
    float ra = a - __bfloat162float(ha), rb = b - __bfloat162float(hb);
    __nv_bfloat16 la = __float2bfloat16(ra), lb = __float2bfloat16(rb);
    hi = (u32)__bfloat16_as_ushort(ha) | ((u32)__bfloat16_as_ushort(hb) << 16);
    lo = (u32)__bfloat16_as_ushort(la) | ((u32)__bfloat16_as_ushort(lb) << 16);
}

// byte offset inside a 64-row x 128B tile, XOR-swizzled for conflict-free ldmatrix
__device__ __forceinline__ u32 off128(int row, int quad) {
    return (u32)((row << 7) + (((quad ^ (row & 7)) << 4)));
}

// ============================================================================
// One-time W transpose + bf16 hi/lo split: g_wt[mat*2+split][n][k]
// ============================================================================
__global__ void wsplit_kernel(const float* __restrict__ Wq,
                              const float* __restrict__ Wk,
                              const float* __restrict__ Wv)
{
    int idx = blockIdx.x * 256 + threadIdx.x;
    int k   = idx & 1023;
    int n   = (idx >> 10) & 63;
    int mat = idx >> 16;
    const float* W = (mat == 0) ? Wq : (mat == 1) ? Wk : Wv;
    float x = W[k * 64 + n];
    __nv_bfloat16 h = __float2bfloat16(x);
    float r = x - __bfloat162float(h);
    __nv_bfloat16 l = __float2bfloat16(r);
    g_wt[(mat * 2 + 0) * 65536 + n * 1024 + k] = h;
    g_wt[(mat * 2 + 1) * 65536 + n * 1024 + k] = l;
}

// ============================================================================
// QKV projection via mma.sync bf16 3-pass split (validated). Writes q/k/v as
// bf16 hi/lo (q/k row-major, v tile-transposed).  UNCHANGED from 172.8 run.
// ============================================================================
__global__ void __launch_bounds__(256) qkv_mma_kernel(
    const float* __restrict__ x,
    const float* __restrict__ bq, const float* __restrict__ bk,
    const float* __restrict__ bv)
{
    __shared__ __align__(16) char sA[2][2][128 * 32];
    __shared__ __align__(16) char sB[2][2][192 * 32];
    __shared__ float bias_s[192];

    const int tid    = threadIdx.x;
    const int lane   = tid & 31;
    const int wid    = tid >> 5;
    const int warp_m = wid >> 1;
    const int warp_n = wid & 1;
    const int mBase  = blockIdx.x * 128;

    if (tid < 192)
        bias_s[tid] = (tid < 64) ? bq[tid]
                    : (tid < 128) ? bk[tid - 64] : bv[tid - 128];

    const u32 aBase = smem_u32(sA);
    const u32 bBase = smem_u32(sB);

    float acc[2][12][4];
    #pragma unroll
    for (int mt = 0; mt < 2; mt++)
        #pragma unroll
        for (int nt = 0; nt < 12; nt++)
            #pragma unroll
            for (int e = 0; e < 4; e++) acc[mt][nt][e] = 0.f;

    const int xr = tid >> 1, xq = tid & 1;
    const u32 xoff = xr * 32 + ((xq ^ ((xr >> 2) & 1)) << 4);
    const float* xsrc = &x[(size_t)(mBase + xr) * H_ + xq * 8];

    int w_split[3], w_srcoff[3]; u32 w_off[3];
    #pragma unroll
    for (int i = 0; i < 3; i++) {
        int q = i * 256 + tid;
        int ms = q >> 7;
        int idx = q & 127;
        int nn = idx >> 1, qq = idx & 1;
        int r  = (ms >> 1) * 64 + nn;
        w_split[i] = ms & 1;
        w_srcoff[i] = (ms * 64 + nn) * 1024 + qq * 8;
        w_off[i] = r * 32 + ((qq ^ ((r >> 2) & 1)) << 4);
    }

    u32 a_off[2];
    {
        int arow = warp_m * 32 + (lane & 15);
        u32 aq = lane >> 4;
        #pragma unroll
        for (int mt = 0; mt < 2; mt++) {
            int r = arow + mt * 16;
            a_off[mt] = r * 32 + ((aq ^ ((r >> 2) & 1)) << 4);
        }
    }
    u32 b_off[12];
    {
        int brow = lane & 7;
        u32 bqd = (lane >> 3) & 1;
        #pragma unroll
        for (int nt = 0; nt < 12; nt++) {
            int r = warp_n * 96 + nt * 8 + brow;
            b_off[nt] = r * 32 + ((bqd ^ ((r >> 2) & 1)) << 4);
        }
    }

    float4 xv0 = *(const float4*)(xsrc);
    float4 xv1 = *(const float4*)(xsrc + 4);
    uint4 wv[3];
    #pragma unroll
    for (int i = 0; i < 3; i++)
        wv[i] = *(const uint4*)&g_wt[w_srcoff[i]];

    for (int c = 0; c < 64; ++c) {
        const int buf = c & 1;
        {
            float f[8] = { xv0.x, xv0.y, xv0.z, xv0.w, xv1.x, xv1.y, xv1.z, xv1.w };
            u32 hp[4], lp[4];
            #pragma unroll
            for (int j = 0; j < 4; ++j)
                bsplit2(f[2*j], f[2*j+1], hp[j], lp[j]);
            *(uint4*)&sA[buf][0][xoff] = make_uint4(hp[0], hp[1], hp[2], hp[3]);
            *(uint4*)&sA[buf][1][xoff] = make_uint4(lp[0], lp[1], lp[2], lp[3]);
            #pragma unroll
            for (int i = 0; i < 3; i++)
                *(uint4*)&sB[buf][w_split[i]][w_off[i]] = wv[i];
        }
        __syncthreads();

        if (c < 63) {
            xv0 = *(const float4*)(xsrc + (c + 1) * 16);
            xv1 = *(const float4*)(xsrc + (c + 1) * 16 + 4);
            #pragma unroll
            for (int i = 0; i < 3; i++)
                wv[i] = *(const uint4*)&g_wt[w_srcoff[i] + (c + 1) * 16];
        }

        const u32 aH = aBase + (buf * 2 + 0) * 4096;
        const u32 aL = aBase + (buf * 2 + 1) * 4096;
        const u32 bH = bBase + (buf * 2 + 0) * 6144;
        const u32 bL = bBase + (buf * 2 + 1) * 6144;

        u32 ah[2][4], al[2][4];
        #pragma unroll
        for (int mt = 0; mt < 2; mt++) {
            LDSM_X4(ah[mt], aH + a_off[mt]);
            LDSM_X4(al[mt], aL + a_off[mt]);
        }
        #pragma unroll
        for (int nt = 0; nt < 12; nt++) {
            u32 bh[2], bl[2];
            LDSM_X2(bh, bH + b_off[nt]);
            LDSM_X2(bl, bL + b_off[nt]);
            #pragma unroll
            for (int mt = 0; mt < 2; mt++) {
                MMA_BF16(acc[mt][nt], ah[mt], bh);
                MMA_BF16(acc[mt][nt], ah[mt], bl);
                MMA_BF16(acc[mt][nt], al[mt], bh);
            }
        }
        __syncthreads();
    }

    // ---- epilogue: bias add, bf16 hi/lo split outputs ----
    #pragma unroll
    for (int mt = 0; mt < 2; mt++) {
        #pragma unroll
        for (int nt = 0; nt < 12; nt++) {
            const int ng  = warp_n * 96 + nt * 8 + (lane & 3) * 2;
            const int mat = ng >> 6;
            const int col = ng & 63;
            const int r0  = mBase + warp_m * 32 + mt * 16 + (lane >> 2);
            const float b0 = bias_s[ng], b1 = bias_s[ng + 1];
            const float v00 = acc[mt][nt][0] + b0, v01 = acc[mt][nt][1] + b1;
            const float v10 = acc[mt][nt][2] + b0, v11 = acc[mt][nt][3] + b1;
            if (mat < 2) {
                __nv_bfloat16* dh = mat ? g_kh : g_qh;
                __nv_bfloat16* dl = mat ? g_kl : g_ql;
                u32 h0, l0, h1, l1;
                bsplit2(v00, v01, h0, l0);
                bsplit2(v10, v11, h1, l1);
                *(u32*)&dh[(size_t)r0 * D_ + col]       = h0;
                *(u32*)&dl[(size_t)r0 * D_ + col]       = l0;
                *(u32*)&dh[(size_t)(r0 + 8) * D_ + col] = h1;
                *(u32*)&dl[(size_t)(r0 + 8) * D_ + col] = l1;
            } else {
                #pragma unroll
                for (int e = 0; e < 4; e++) {
                    const int rr = r0 + (e >> 1) * 8;
                    const int cc = col + (e & 1);
                    const float vv = (e == 0) ? v00 : (e == 1) ? v01 : (e == 2) ? v10 : v11;
                    const int bb = rr >> 11, ss = rr & 2047;
                    const int tile = ss >> 6, kk = ss & 63;
                    size_t idx = (((size_t)bb * 32 + tile) * 64 + cc) * 64 + kk;
                    __nv_bfloat16 h = __float2bfloat16(vv);
                    float r = vv - __bfloat162float(h);
                    g_vth[idx] = h;
                    g_vtl[idx] = __float2bfloat16(r);
                }
            }
        }
    }
}

// ============================================================================
// Causal flash attention, mma.sync bf16, cp.async-pipelined staging:
//  - Q fragments loaded straight from gmem into registers (no sQ buffer)
//  - P has its own smem buffer -> K_{t+1} prefetch overlaps softmax+pass2,
//    V_t arrives under pass1; staging latency hidden
//  - B operands via ldmatrix.x4 over n-tile pairs (half the LDSM count)
// Grid 16 x 8 pairing schedule {p, 31-p} = uniform 33 tiles/CTA (validated).
// 128 threads = 4 warps; warp w owns rows [w*16, w*16+16).
// out = (softmax(QK^T masked)/32) @ V.
// ============================================================================
__global__ void __launch_bounds__(128) attn_kernel(float* __restrict__ out)
{
    const int b    = blockIdx.y;
    const int pp   = blockIdx.x;             // 0..15
    const int tid  = threadIdx.x;
    const int lane = tid & 31;
    const int wid  = tid >> 5;

    __shared__ __align__(16) char sK[2][8192];   // K hi/lo, 64 rows x 128B
    __shared__ __align__(16) char sV[2][8192];   // Vt hi/lo
    __shared__ __align__(16) char sP[2][8192];   // P hi/lo

    const u32 aK0 = smem_u32(sK[0]), aK1 = smem_u32(sK[1]);
    const u32 aV0 = smem_u32(sV[0]), aV1 = smem_u32(sV[1]);
    const u32 aP0 = smem_u32(sP[0]), aP1 = smem_u32(sP[1]);

    const __nv_bfloat16* gqh = g_qh  + (size_t)b * S_ * D_;
    const __nv_bfloat16* gql = g_ql  + (size_t)b * S_ * D_;
    const __nv_bfloat16* gkh = g_kh  + (size_t)b * S_ * D_;
    const __nv_bfloat16* gkl = g_kl  + (size_t)b * S_ * D_;
    const __nv_bfloat16* gvh = g_vth + (size_t)b * S_ * D_;
    const __nv_bfloat16* gvl = g_vtl + (size_t)b * S_ * D_;
    float* gout = out + (size_t)b * S_ * D_;

    // fragment geometry
    const int aRow  = wid * 16 + (lane & 15);           // P ldmatrix rows
    const int aQd   = lane >> 4;                        // k16-half for A x4
    const int bRow4 = ((lane >> 4) << 3) + (lane & 7);  // + np*16
    const int bQd   = (lane >> 3) & 1;                  // k8-half within k16
    const int rl    = wid * 16 + (lane >> 2);           // acc row (c0/c1)
    const int rh    = rl + 8;                           // acc row (c2/c3)
    const int cB    = (lane & 3) * 2;                   // col within n-tile

    // staging geometry (cp.async, 8 x 16B per thread per tensor)
    const int stg_sp = tid >> 6;        // used via idx decomposition below

    for (int h = 0; h < 2; h++) {
        const int mIdx  = h ? (31 - pp) : pp;
        const int mBase = mIdx * 64;

        // ---- Q fragments straight from gmem (A-frag layout, hi/lo) ----
        u32 qfh[4][4], qfl[4][4];
        {
            const int qr = mBase + rl;      // row for a0/a2 (rl uses lane>>2)
            const int qc = cB;              // cols (lane&3)*2
            #pragma unroll
            for (int kc = 0; kc < 4; kc++) {
                const int c0 = kc * 16 + qc;
                qfh[kc][0] = *(const u32*)&gqh[(size_t)qr * D_ + c0];
                qfh[kc][1] = *(const u32*)&gqh[(size_t)(qr + 8) * D_ + c0];
                qfh[kc][2] = *(const u32*)&gqh[(size_t)qr * D_ + c0 + 8];
                qfh[kc][3] = *(const u32*)&gqh[(size_t)(qr + 8) * D_ + c0 + 8];
                qfl[kc][0] = *(const u32*)&gql[(size_t)qr * D_ + c0];
                qfl[kc][1] = *(const u32*)&gql[(size_t)(qr + 8) * D_ + c0];
                qfl[kc][2] = *(const u32*)&gql[(size_t)qr * D_ + c0 + 8];
                qfl[kc][3] = *(const u32*)&gql[(size_t)(qr + 8) * D_ + c0 + 8];
            }
        }

        // ---- prime pipeline: prefetch K_0 then V_0 (separate groups) ----
        if (h == 1) __syncthreads();   // half-0 smem reads fully done
        #pragma unroll
        for (int i = 0; i < 8; i++) {
            int idx = i * 128 + tid;
            int sp = idx >> 9, r = (idx >> 3) & 63, qd = idx & 7;
            const __nv_bfloat16* src = (sp ? gkl : gkh) + (size_t)r * D_ + qd * 8;
            CP_ASYNC16((sp ? aK1 : aK0) + off128(r, qd), src);
        }
        CP_COMMIT();
        #pragma unroll
        for (int i = 0; i < 8; i++) {
            int idx = i * 128 + tid;
            int sp = idx >> 9, r = (idx >> 3) & 63, qd = idx & 7;
            const __nv_bfloat16* src = (sp ? gvl : gvh) + (size_t)r * D_ + qd * 8;
            CP_ASYNC16((sp ? aV1 : aV0) + off128(r, qd), src);
        }
        CP_COMMIT();

        float accO[8][4];
        #pragma unroll
        for (int nt = 0; nt < 8; nt++)
            #pragma unroll
            for (int e = 0; e < 4; e++) accO[nt][e] = 0.f;
        float m0 = -1e30f, m1 = -1e30f, l0 = 0.f, l1 = 0.f;

        for (int t = 0; t <= mIdx; t++) {
            // pending groups: K_t, V_t  ->  wait until K_t done (mine)
            CP_WAIT1();
            __syncthreads();   // all threads' K_t visible

            // ---- pass 1: S = Q K^T (3-pass bf16 split), B via x4 ----
            float accS[8][4];
            #pragma unroll
            for (int nt = 0; nt < 8; nt++)
                #pragma unroll
                for (int e = 0; e < 4; e++) accS[nt][e] = 0.f;

            #pragma unroll
            for (int kc = 0; kc < 4; kc++) {
                #pragma unroll
                for (int np = 0; np < 4; np++) {
                    const u32 boff = off128(np * 16 + bRow4, 2 * kc + bQd);
                    u32 bh[4], bl[4];
                    LDSM_X4(bh, aK0 + boff);
                    LDSM_X4(bl, aK1 + boff);
                    MMA_BF16(accS[2*np],   qfh[kc], bh);
                    MMA_BF16(accS[2*np],   qfh[kc], bl);
                    MMA_BF16(accS[2*np],   qfl[kc], bh);
                    MMA_BF16(accS[2*np+1], qfh[kc], bh + 2);
                    MMA_BF16(accS[2*np+1], qfh[kc], bl + 2);
                    MMA_BF16(accS[2*np+1], qfl[kc], bh + 2);
                }
            }
            __syncthreads();   // all warps done reading K_t

            // ---- online softmax; P -> sP (own-warp rows only) ----
            if (t == mIdx) {
                #pragma unroll
                for (int nt = 0; nt < 8; nt++) {
                    const int c0 = nt * 8 + cB;
                    if (c0 > rl)     accS[nt][0] = -1e30f;
                    if (c0 + 1 > rl) accS[nt][1] = -1e30f;
                    if (c0 > rh)     accS[nt][2] = -1e30f;
                    if (c0 + 1 > rh) accS[nt][3] = -1e30f;
                }
            }
            float mx0 = -1e30f, mx1 = -1e30f;
            #pragma unroll
            for (int nt = 0; nt < 8; nt++) {
                mx0 = fmaxf(mx0, fmaxf(accS[nt][0], accS[nt][1]));
                mx1 = fmaxf(mx1, fmaxf(accS[nt][2], accS[nt][3]));
            }
            mx0 = fmaxf(mx0, __shfl_xor_sync(0xffffffffu, mx0, 1));
            mx0 = fmaxf(mx0, __shfl_xor_sync(0xffffffffu, mx0, 2));
            mx1 = fmaxf(mx1, __shfl_xor_sync(0xffffffffu, mx1, 1));
            mx1 = fmaxf(mx1, __shfl_xor_sync(0xffffffffu, mx1, 2));

            const float mn0 = fmaxf(m0, mx0), mn1 = fmaxf(m1, mx1);
            const float cr0 = __expf(m0 - mn0), cr1 = __expf(m1 - mn1);
            m0 = mn0; m1 = mn1;

            float ps0 = 0.f, ps1 = 0.f;
            #pragma unroll
            for (int nt = 0; nt < 8; nt++) {
                const float p00 = __expf(accS[nt][0] - mn0);
                const float p01 = __expf(accS[nt][1] - mn0);
                const float p10 = __expf(accS[nt][2] - mn1);
                const float p11 = __expf(accS[nt][3] - mn1);
                ps0 += p00 + p01;
                ps1 += p10 + p11;
                u32 hlo, llo, hhi, lhi;
                bsplit2(p00, p01, hlo, llo);
                bsplit2(p10, p11, hhi, lhi);
                const u32 oLo = off128(rl, nt) + cB * 2;
                const u32 oHi = off128(rh, nt) + cB * 2;
                *(u32*)&sP[0][oLo] = hlo;
                *(u32*)&sP[1][oLo] = llo;
                *(u32*)&sP[0][oHi] = hhi;
                *(u32*)&sP[1][oHi] = lhi;
            }
            ps0 += __shfl_xor_sync(0xffffffffu, ps0, 1);
            ps0 += __shfl_xor_sync(0xffffffffu, ps0, 2);
            ps1 += __shfl_xor_sync(0xffffffffu, ps1, 1);
            ps1 += __shfl_xor_sync(0xffffffffu, ps1, 2);
            l0 = l0 * cr0 + ps0;
            l1 = l1 * cr1 + ps1;
            #pragma unroll
            for (int nt = 0; nt < 8; nt++) {
                accO[nt][0] *= cr0; accO[nt][1] *= cr0;
                accO[nt][2] *= cr1; accO[nt][3] *= cr1;
            }
            __syncwarp();   // own-warp P stores visible to own-warp ldmatrix

            // ---- prefetch K_{t+1} into sK (overlaps pass2) ----
            if (t < mIdx) {
                #pragma unroll
                for (int i = 0; i < 8; i++) {
                    int idx = i * 128 + tid;
                    int sp = idx >> 9, r = (idx >> 3) & 63, qd = idx & 7;
                    const __nv_bfloat16* src =
                        (sp ? gkl : gkh) + (size_t)((t + 1) * 64 + r) * D_ + qd * 8;
                    CP_ASYNC16((sp ? aK1 : aK0) + off128(r, qd), src);
                }
            }
            CP_COMMIT();      // pending: V_t, K_{t+1}
            CP_WAIT1();       // V_t done (mine)
            __syncthreads();  // all threads' V_t visible

            // ---- pass 2: O += P V (A = P from sP, B = Vt via x4) ----
            #pragma unroll
            for (int kc = 0; kc < 4; kc++) {
                const u32 aoff = off128(aRow, 2 * kc + aQd);
                u32 ah[4], al[4];
                LDSM_X4(ah, aP0 + aoff);
                LDSM_X4(al, aP1 + aoff);
                #pragma unroll
                for (int np = 0; np < 4; np++) {
                    const u32 boff = off128(np * 16 + bRow4, 2 * kc + bQd);
                    u32 bh[4], bl[4];
                    LDSM_X4(bh, aV0 + boff);
                    LDSM_X4(bl, aV1 + boff);
                    MMA_BF16(accO[2*np],   ah, bh);
                    MMA_BF16(accO[2*np],   ah, bl);
                    MMA_BF16(accO[2*np],   al, bh);
                    MMA_BF16(accO[2*np+1], ah, bh + 2);
                    MMA_BF16(accO[2*np+1], ah, bl + 2);
                    MMA_BF16(accO[2*np+1], al, bh + 2);
                }
            }
            __syncthreads();  // all done reading V_t (and sP)

            // ---- prefetch V_{t+1} into sV (overlaps next pass1) ----
            if (t < mIdx) {
                #pragma unroll
                for (int i = 0; i < 8; i++) {
                    int idx = i * 128 + tid;
                    int sp = idx >> 9, r = (idx >> 3) & 63, qd = idx & 7;
                    const __nv_bfloat16* src =
                        (sp ? gvl : gvh) + (size_t)((t + 1) * 64 + r) * D_ + qd * 8;
                    CP_ASYNC16((sp ? aV1 : aV0) + off128(r, qd), src);
                }
            }
            CP_COMMIT();      // pending: K_{t+1}, V_{t+1}
        }

        // ---- epilogue: /l (softmax norm) and /sqrt(H)=32 ----
        const float i0 = 1.0f / (l0 * 32.0f);
        const float i1 = 1.0f / (l1 * 32.0f);
        #pragma unroll
        for (int nt = 0; nt < 8; nt++) {
            const int col = nt * 8 + cB;
            *(float2*)&gout[(size_t)(mBase + rl) * D_ + col] =
                make_float2(accO[nt][0] * i0, accO[nt][1] * i0);
            *(float2*)&gout[(size_t)(mBase + rh) * D_ + col] =
                make_float2(accO[nt][2] * i1, accO[nt][3] * i1);
        }
    }
    (void)stg_sp;
}

extern "C" void kernel_launch(void* const* d_in, const int* in_sizes, int n_in,
                              void* d_out, int out_size)
{
    const float* x  = (const float*)d_in[0];
    const float* Wq = (const float*)d_in[1];
    const float* bq = (const float*)d_in[2];
    const float* Wk = (const float*)d_in[3];
    const float* bk = (const float*)d_in[4];
    const float* Wv = (const float*)d_in[5];
    const float* bv = (const float*)d_in[6];
    float* out = (float*)d_out;

    wsplit_kernel<<<768, 256>>>(Wq, Wk, Wv);
    qkv_mma_kernel<<<128, 256>>>(x, bq, bk, bv);
    attn_kernel<<<dim3(16, B_), 128>>>(out);
}